// round 5
// baseline (speedup 1.0000x reference)
#include <cuda_runtime.h>
#include <math.h>
#include <stdint.h>

#define BB 8
#define CC 64
#define HH 256
#define WW 256
#define EE 8192
#define HWSZ 65536
typedef unsigned long long u64;

__device__ float g_q[8*8*64*EE];
__device__ float g_k[8*8*64*EE];
__device__ float g_v[8*8*64*EE];
__device__ float g_Sp[16*64*4096];
__device__ float g_P[64*4096];
__device__ float g_y[BB*CC*HWSZ];
__device__ float g_x1[BB*CC*HWSZ];
__device__ float g_t[BB*CC*HWSZ];
__device__ float g_wqkvT[192*64];   // [oc(q|k|v)][ci], tf32-rounded
__device__ float g_bqkv[192];
__device__ float g_wt[3*36864];     // conv: [tap][ci][oc], tf32-rounded

__device__ __forceinline__ int refl(int i, int n){
    if (i < 0) i = -i; if (i >= n) i = 2*n-2-i; return i; }
__device__ __forceinline__ float lrelu(float v){ return v > 0.f ? v : 0.2f*v; }
__device__ __forceinline__ uint32_t f2tf32(float f){
    uint32_t u; asm("cvt.rna.tf32.f32 %0, %1;" : "=r"(u) : "f"(f)); return u; }
__device__ __forceinline__ float tf32r(float f){ return __uint_as_float(f2tf32(f)); }
__device__ __forceinline__ float4 r4(float4 v){
    v.x = tf32r(v.x); v.y = tf32r(v.y); v.z = tf32r(v.z); v.w = tf32r(v.w); return v; }

__device__ __forceinline__ void mma8(float* c, uint32_t a0, uint32_t a1, uint32_t a2,
                                     uint32_t a3, uint32_t b0, uint32_t b1){
    asm("mma.sync.aligned.m16n8k8.row.col.f32.tf32.tf32.f32 "
        "{%0,%1,%2,%3},{%4,%5,%6,%7},{%8,%9},{%0,%1,%2,%3};"
        : "+f"(c[0]),"+f"(c[1]),"+f"(c[2]),"+f"(c[3])
        : "r"(a0),"r"(a1),"r"(a2),"r"(a3),"r"(b0),"r"(b1));
}
#define FU(x) __float_as_uint(x)

// ---------- weight transform ----------
__global__ void xform_kernel(const float* __restrict__ wq, const float* __restrict__ bq,
                             const float* __restrict__ wk, const float* __restrict__ bk,
                             const float* __restrict__ wv, const float* __restrict__ bv,
                             const float* __restrict__ wo, const float* __restrict__ wf1,
                             const float* __restrict__ wf2){
    int idx = blockIdx.x*256 + threadIdx.x;
    if (idx < 12288){
        int t3 = idx/4096, r2 = idx - t3*4096;
        float v = (t3==0) ? wq[r2] : (t3==1 ? wk[r2] : wv[r2]);
        g_wqkvT[idx] = tf32r(v);
    }
    if (idx < 192)
        g_bqkv[idx] = (idx<64) ? bq[idx] : (idx<128 ? bk[idx-64] : bv[idx-128]);
    if (idx < 36864){
        int tap = idx>>12, rem = idx&4095, ci = rem>>6, oc = rem&63;
        int s = (oc*64+ci)*9 + tap;
        g_wt[idx]           = tf32r(wo[s]);
        g_wt[36864 + idx]   = tf32r(wf1[s]);
        g_wt[2*36864 + idx] = tf32r(wf2[s]);
    }
}

// ---------- qkv 1x1 conv via mma: M=oc(192), N=px(128), K=ci(64) ----------
__global__ __launch_bounds__(256) void qkv_kernel(const float* __restrict__ x){
    extern __shared__ float sm[];
    float* Ws = sm;                 // [192][72]
    float* Xn = sm + 13824;         // [64][136]
    const int tid = threadIdx.x, w = tid>>5, gid = (tid&31)>>2, tig = tid&3;
    const int b = blockIdx.z, y = blockIdx.y, x0 = blockIdx.x*128;
    for (int i = tid; i < 3072; i += 256){
        int oc = i>>4, c4 = (i&15)<<2;
        *(float4*)&Ws[oc*72 + c4] = *(const float4*)&g_wqkvT[oc*64 + c4];
    }
    for (int i = tid; i < 2048; i += 256){
        int ci = i>>5, p4 = (i&31)<<2;
        float4 v = r4(*(const float4*)&x[(b*64+ci)*HWSZ + y*256 + x0 + p4]);
        *(float4*)&Xn[ci*136 + p4] = v;
    }
    __syncthreads();
    const int mg = (w&3)*3, nb = (w>>2)*64;
    float acc[3][8][4] = {};
    #pragma unroll
    for (int kk = 0; kk < 8; kk++){
        uint32_t bf0[8], bf1[8];
        #pragma unroll
        for (int nt = 0; nt < 8; nt++){
            bf0[nt] = FU(Xn[(kk*8+tig)*136 + nb + nt*8 + gid]);
            bf1[nt] = FU(Xn[(kk*8+tig+4)*136 + nb + nt*8 + gid]);
        }
        #pragma unroll
        for (int mt = 0; mt < 3; mt++){
            const float* ap = &Ws[((mg+mt)*16+gid)*72 + kk*8 + tig];
            uint32_t a0 = FU(ap[0]), a1 = FU(ap[8*72]), a2 = FU(ap[4]), a3 = FU(ap[8*72+4]);
            #pragma unroll
            for (int nt = 0; nt < 8; nt++)
                mma8(acc[mt][nt], a0, a1, a2, a3, bf0[nt], bf1[nt]);
        }
    }
    const int pyo = (y&31)*32, wrow = (y>>5)*8;
    #pragma unroll
    for (int mt = 0; mt < 3; mt++){
        int ocA = (mg+mt)*16 + gid, ocB = ocA + 8;
        float bA = g_bqkv[ocA], bB = g_bqkv[ocB];
        int t3A = ocA>>6, cA = ocA&63;
        int t3B = ocB>>6, cB = ocB&63;
        float* pA = (t3A==0?g_q:(t3A==1?g_k:g_v)) + ((u64)(b*8+(cA>>3))*64)*EE + (cA&7)*1024;
        float* pB = (t3B==0?g_q:(t3B==1?g_k:g_v)) + ((u64)(b*8+(cB>>3))*64)*EE + (cB&7)*1024;
        #pragma unroll
        for (int nt = 0; nt < 8; nt++){
            int px = x0 + nb + nt*8 + tig*2;
            int wo2 = (wrow + (px>>5))*EE + pyo + (px&31);
            *(float2*)&pA[wo2] = make_float2(acc[mt][nt][0]+bA, acc[mt][nt][1]+bA);
            *(float2*)&pB[wo2] = make_float2(acc[mt][nt][2]+bB, acc[mt][nt][3]+bB);
        }
    }
}

// ---------- scores via mma: per (bh, e-slice 512): S[64,64] partial ----------
__global__ __launch_bounds__(128) void attn_scores_kernel(){
    __shared__ float Qs[64*72];
    __shared__ float Ks[64*72];
    const int bh = blockIdx.x>>4, sl = blockIdx.x&15, e0 = sl*512;
    const int tid = threadIdx.x, w = tid>>5, gid = (tid&31)>>2, tig = tid&3;
    const float* Qg = g_q + (u64)bh*64*EE;
    const float* Kg = g_k + (u64)bh*64*EE;
    float acc[8][4] = {};
    for (int ec = 0; ec < 8; ec++){
        __syncthreads();
        for (int i = tid; i < 1024; i += 128){
            int q = i>>4, e4 = (i&15)<<2;
            *(float4*)&Qs[q*72+e4] = r4(*(const float4*)&Qg[q*EE + e0 + ec*64 + e4]);
            *(float4*)&Ks[q*72+e4] = r4(*(const float4*)&Kg[q*EE + e0 + ec*64 + e4]);
        }
        __syncthreads();
        #pragma unroll
        for (int kk = 0; kk < 8; kk++){
            const float* ap = &Qs[(w*16+gid)*72 + kk*8 + tig];
            uint32_t a0 = FU(ap[0]), a1 = FU(ap[8*72]), a2 = FU(ap[4]), a3 = FU(ap[8*72+4]);
            #pragma unroll
            for (int nt = 0; nt < 8; nt++){
                const float* bp = &Ks[(nt*8+gid)*72 + kk*8 + tig];
                mma8(acc[nt], a0, a1, a2, a3, FU(bp[0]), FU(bp[4]));
            }
        }
    }
    float* Sp = g_Sp + (u64)(sl*64+bh)*4096;
    int qA = w*16+gid, qB = qA+8;
    #pragma unroll
    for (int nt = 0; nt < 8; nt++){
        int key = nt*8 + tig*2;
        *(float2*)&Sp[qA*64+key] = make_float2(acc[nt][0], acc[nt][1]);
        *(float2*)&Sp[qB*64+key] = make_float2(acc[nt][2], acc[nt][3]);
    }
}

// ---------- softmax: one warp per (bh,q) row ----------
__global__ void softmax_kernel(){
    const int r = blockIdx.x*8 + (threadIdx.x>>5);
    const int bh = r>>6, q = r&63, lane = threadIdx.x&31;
    const float scale = 0.011048543456039806f;
    float s0 = 0.f, s1 = 0.f;
    #pragma unroll
    for (int sl = 0; sl < 16; sl++){
        const float* p = g_Sp + (u64)(sl*64+bh)*4096 + q*64;
        s0 += p[lane]; s1 += p[lane+32];
    }
    s0 *= scale; s1 *= scale;
    float mx = fmaxf(s0, s1);
    for (int o = 16; o; o >>= 1) mx = fmaxf(mx, __shfl_xor_sync(~0u, mx, o));
    float e0 = __expf(s0-mx), e1 = __expf(s1-mx);
    float sum = e0+e1;
    for (int o = 16; o; o >>= 1) sum += __shfl_xor_sync(~0u, sum, o);
    float inv = 1.f/sum;
    g_P[bh*4096 + q*64 + lane]    = e0*inv;
    g_P[bh*4096 + q*64 + lane+32] = e1*inv;
}

// ---------- PV via mma: per (bh, e-chunk 256): Y[64,256] = P[64,64] V[64,256] ----------
__global__ __launch_bounds__(128) void attn_pv_kernel(){
    extern __shared__ float sm[];
    float* Ps = sm;             // [64][72]
    float* Vs = sm + 4608;      // [64][264]
    const int bh = blockIdx.x>>5, ec = blockIdx.x&31, e0 = ec*256;
    const int tid = threadIdx.x, w = tid>>5, gid = (tid&31)>>2, tig = tid&3;
    for (int i = tid; i < 1024; i += 128){
        int q = i>>4, k4 = (i&15)<<2;
        *(float4*)&Ps[q*72+k4] = r4(*(const float4*)&g_P[bh*4096 + q*64 + k4]);
    }
    const float* Vg = g_v + (u64)bh*64*EE;
    for (int i = tid; i < 4096; i += 128){
        int key = i>>6, e4 = (i&63)<<2;
        *(float4*)&Vs[key*264+e4] = r4(*(const float4*)&Vg[key*EE + e0 + e4]);
    }
    __syncthreads();
    float acc[32][4] = {};
    #pragma unroll
    for (int kk = 0; kk < 8; kk++){
        const float* ap = &Ps[(w*16+gid)*72 + kk*8 + tig];
        uint32_t a0 = FU(ap[0]), a1 = FU(ap[8*72]), a2 = FU(ap[4]), a3 = FU(ap[8*72+4]);
        const float* b0p = &Vs[(kk*8+tig)*264 + gid];
        const float* b1p = &Vs[(kk*8+tig+4)*264 + gid];
        #pragma unroll
        for (int nt = 0; nt < 32; nt++)
            mma8(acc[nt], a0, a1, a2, a3, FU(b0p[nt*8]), FU(b1p[nt*8]));
    }
    const int b = bh>>3, h = bh&7;
    const int qA = w*16+gid, qB = qA+8;
    const int sA = ((qA>>3)*32)*256 + (qA&7)*32;
    const int sB = ((qB>>3)*32)*256 + (qB&7)*32;
    #pragma unroll
    for (int nt = 0; nt < 32; nt++){
        int eg = e0 + nt*8 + tig*2;
        int d = eg>>10, py = (eg>>5)&31, px = eg&31;
        float* base = g_y + (u64)(b*64 + h*8 + d)*HWSZ + py*256 + px;
        *(float2*)&base[sA] = make_float2(acc[nt][0], acc[nt][1]);
        *(float2*)&base[sB] = make_float2(acc[nt][2], acc[nt][3]);
    }
}

// ---------- conv 3x3 via mma: tile 8x32 px, M=256, N=64 oc, K=576 ----------
template<int D>
__global__ __launch_bounds__(128) void conv_mma_kernel(
        const float* __restrict__ src, const float* __restrict__ gw,
        const float* __restrict__ bias, const float* __restrict__ resid,
        float* __restrict__ dst){
    constexpr int ROWS = 8 + 2*D, COLS = 32 + 2*D, RC = ROWS*COLS;
    constexpr int SA = (D == 1) ? 344 : 440;
    extern __shared__ float sm[];
    float* raw = sm;            // [64][SA]
    float* bs  = sm + 64*SA;    // [64][72]
    __shared__ int yoff[12], xoff[36];
    const int tid = threadIdx.x, w = tid>>5, gid = (tid&31)>>2, tig = tid&3;
    const int b = blockIdx.z, y0 = blockIdx.y*8, x0 = blockIdx.x*32;
    if (tid < ROWS) yoff[tid] = refl(y0 - D + tid, HH)*256;
    if (tid >= 32 && tid < 32+COLS) xoff[tid-32] = refl(x0 - D + (tid-32), WW);
    __syncthreads();
    for (int i = tid; i < 64*RC; i += 128){
        int ci = i/RC, rem = i - ci*RC;
        int r = rem/COLS, c2 = rem - r*COLS;
        raw[ci*SA + rem] = tf32r(src[(u64)(b*64+ci)*HWSZ + yoff[r] + xoff[c2]]);
    }
    float acc[4][8][4] = {};
    for (int tap = 0; tap < 9; tap++){
        __syncthreads();
        for (int f = tid; f < 1024; f += 128){
            int ci = f>>4, o4 = (f&15)<<2;
            *(float4*)&bs[ci*72 + o4] = *(const float4*)&gw[tap*4096 + ci*64 + o4];
        }
        __syncthreads();
        const int dy = tap/3, dx = tap - dy*3;
        #pragma unroll
        for (int kc = 0; kc < 8; kc++){
            const int k0 = kc*8;
            uint32_t bf0[8], bf1[8];
            #pragma unroll
            for (int nt = 0; nt < 8; nt++){
                bf0[nt] = FU(bs[(k0+tig)*72 + nt*8 + gid]);
                bf1[nt] = FU(bs[(k0+tig+4)*72 + nt*8 + gid]);
            }
            #pragma unroll
            for (int mt = 0; mt < 4; mt++){
                const float* ap = &raw[(k0+tig)*SA + (w*2 + (mt>>1) + dy*D)*COLS
                                       + (mt&1)*16 + gid + dx*D];
                uint32_t a0 = FU(ap[0]), a1 = FU(ap[8]);
                uint32_t a2 = FU(ap[4*SA]), a3 = FU(ap[4*SA+8]);
                #pragma unroll
                for (int nt = 0; nt < 8; nt++)
                    mma8(acc[mt][nt], a0, a1, a2, a3, bf0[nt], bf1[nt]);
            }
        }
    }
    float bv0[8], bv1[8];
    #pragma unroll
    for (int nt = 0; nt < 8; nt++){
        bv0[nt] = __ldg(&bias[nt*8 + tig*2]);
        bv1[nt] = __ldg(&bias[nt*8 + tig*2 + 1]);
    }
    #pragma unroll
    for (int mt = 0; mt < 4; mt++){
        const int yy = y0 + w*2 + (mt>>1);
        const int rowbase = b*64*HWSZ + yy*256 + x0 + (mt&1)*16 + gid;
        #pragma unroll
        for (int nt = 0; nt < 8; nt++){
            const int a00 = rowbase + (nt*8 + tig*2)*HWSZ;
            float v0 = lrelu(acc[mt][nt][0] + bv0[nt]);
            float v1 = lrelu(acc[mt][nt][1] + bv1[nt]);
            float v2 = lrelu(acc[mt][nt][2] + bv0[nt]);
            float v3 = lrelu(acc[mt][nt][3] + bv1[nt]);
            if (resid){
                v0 += resid[a00];
                v1 += resid[a00 + HWSZ];
                v2 += resid[a00 + 8];
                v3 += resid[a00 + HWSZ + 8];
            }
            dst[a00]            = v0;
            dst[a00 + HWSZ]     = v1;
            dst[a00 + 8]        = v2;
            dst[a00 + HWSZ + 8] = v3;
        }
    }
}

extern "C" void kernel_launch(void* const* d_in, const int* in_sizes, int n_in,
                              void* d_out, int out_size){
    const float* x   = (const float*)d_in[0];
    const float* wq  = (const float*)d_in[2];
    const float* bq  = (const float*)d_in[3];
    const float* wk  = (const float*)d_in[4];
    const float* bk  = (const float*)d_in[5];
    const float* wv  = (const float*)d_in[6];
    const float* bv  = (const float*)d_in[7];
    const float* wo  = (const float*)d_in[8];
    const float* bo  = (const float*)d_in[9];
    const float* wf1 = (const float*)d_in[10];
    const float* bf1 = (const float*)d_in[11];
    const float* wf2 = (const float*)d_in[12];
    const float* bf2 = (const float*)d_in[13];
    float* out = (float*)d_out;

    float *py, *px1, *pt, *pwt;
    cudaGetSymbolAddress((void**)&py,  g_y);
    cudaGetSymbolAddress((void**)&px1, g_x1);
    cudaGetSymbolAddress((void**)&pt,  g_t);
    cudaGetSymbolAddress((void**)&pwt, g_wt);

    const int QKV_SMEM = (13824 + 8704) * 4;        // 90112
    const int PV_SMEM  = (4608 + 16896) * 4;        // 86016
    const int SM1 = (64*344 + 4608) * 4;            // 106496
    const int SM2 = (64*440 + 4608) * 4;            // 131072
    cudaFuncSetAttribute(qkv_kernel, cudaFuncAttributeMaxDynamicSharedMemorySize, QKV_SMEM);
    cudaFuncSetAttribute(attn_pv_kernel, cudaFuncAttributeMaxDynamicSharedMemorySize, PV_SMEM);
    cudaFuncSetAttribute(conv_mma_kernel<1>, cudaFuncAttributeMaxDynamicSharedMemorySize, SM1);
    cudaFuncSetAttribute(conv_mma_kernel<2>, cudaFuncAttributeMaxDynamicSharedMemorySize, SM2);

    xform_kernel<<<144, 256>>>(wq, bq, wk, bk, wv, bv, wo, wf1, wf2);
    qkv_kernel<<<dim3(2, 256, BB), 256, QKV_SMEM>>>(x);
    attn_scores_kernel<<<1024, 128>>>();
    softmax_kernel<<<512, 256>>>();
    attn_pv_kernel<<<2048, 128, PV_SMEM>>>();
    dim3 cg(8, 32, BB);
    conv_mma_kernel<1><<<cg, 128, SM1>>>(py,  pwt,           bo,  x,    px1);
    conv_mma_kernel<2><<<cg, 128, SM2>>>(px1, pwt + 36864,   bf1, nullptr, pt);
    conv_mma_kernel<1><<<cg, 128, SM1>>>(pt,  pwt + 2*36864, bf2, px1,  out);
}

// round 7
// speedup vs baseline: 2.0578x; 2.0578x over previous
#include <cuda_runtime.h>
#include <cuda_fp16.h>
#include <math.h>
#include <stdint.h>

#define BB 8
#define HH 256
#define WW 256
#define EE 8192
#define HWSZ 65536
typedef unsigned long long u64;
typedef uint32_t u32;

__device__ __half g_qh[64*64*EE];
__device__ __half g_kh[64*64*EE];
__device__ __half g_vh[64*64*EE];
__device__ float  g_Sp[16*64*4096];
__device__ __half g_P[64*4096];
__device__ float  g_y[BB*64*HWSZ];
__device__ float  g_x1[BB*64*HWSZ];
__device__ float  g_t[BB*64*HWSZ];
__device__ __half g_wqkvh[192*72];     // [oc][ci] stride 72
__device__ float  g_bqkv[192];
__device__ __half g_wth[3*9*64*72];    // [conv][tap][oc][ci] stride 72

__device__ __forceinline__ int refl(int i, int n){
    if (i < 0) i = -i; if (i >= n) i = 2*n-2-i; return i; }
__device__ __forceinline__ float lrelu(float v){ return v > 0.f ? v : 0.2f*v; }

__device__ __forceinline__ void mma16(float* c, u32 a0, u32 a1, u32 a2, u32 a3,
                                      u32 b0, u32 b1){
    asm("mma.sync.aligned.m16n8k16.row.col.f32.f16.f16.f32 "
        "{%0,%1,%2,%3},{%4,%5,%6,%7},{%8,%9},{%0,%1,%2,%3};"
        : "+f"(c[0]),"+f"(c[1]),"+f"(c[2]),"+f"(c[3])
        : "r"(a0),"r"(a1),"r"(a2),"r"(a3),"r"(b0),"r"(b1));
}

// ---------- weight transform ----------
__global__ void xform_kernel(const float* __restrict__ wq, const float* __restrict__ bq,
                             const float* __restrict__ wk, const float* __restrict__ bk,
                             const float* __restrict__ wv, const float* __restrict__ bv,
                             const float* __restrict__ wo, const float* __restrict__ wf1,
                             const float* __restrict__ wf2){
    int idx = blockIdx.x*256 + threadIdx.x;
    if (idx < 12288){
        int oc = idx>>6, ci = idx&63;
        int t3 = oc>>6, r = (oc&63)*64 + ci;
        float v = (t3==0) ? wq[r] : (t3==1 ? wk[r] : wv[r]);
        g_wqkvh[oc*72 + ci] = __float2half_rn(v);
    }
    if (idx < 192)
        g_bqkv[idx] = (idx<64) ? bq[idx] : (idx<128 ? bk[idx-64] : bv[idx-128]);
    if (idx < 36864){
        int tap = idx>>12, oc = (idx&4095)>>6, ci = idx&63;
        int s = (oc*64+ci)*9 + tap;
        int d = (tap*64 + oc)*72 + ci;
        g_wth[d]            = __float2half_rn(wo[s]);
        g_wth[41472 + d]    = __float2half_rn(wf1[s]);
        g_wth[2*41472 + d]  = __float2half_rn(wf2[s]);
    }
}

// ---------- qkv 1x1 conv: M=oc192, N=px128, K=ci64 ----------
__global__ __launch_bounds__(256) void qkv_kernel(const float* __restrict__ x){
    extern __shared__ __half smh[];
    __half* Ws = smh;            // [192][72]
    __half* Xn = smh + 13824;    // [128px][72]
    u32* Wsw = (u32*)Ws; u32* Xnw = (u32*)Xn;
    const int tid = threadIdx.x, w = tid>>5, gid = (tid&31)>>2, tig = tid&3;
    const int b = blockIdx.z, y = blockIdx.y, x0 = blockIdx.x*128;
    const u32* gww = (const u32*)g_wqkvh;
    for (int i = tid; i < 6912; i += 256) Wsw[i] = gww[i];
    for (int i = tid; i < 8192; i += 256){
        int ci = i>>7, px = i&127;
        Xn[px*72 + ci] = __float2half_rn(x[(b*64+ci)*HWSZ + y*256 + x0 + px]);
    }
    __syncthreads();
    const int mg = (w&3)*3, nb = (w>>2)*64;
    float acc[3][8][4] = {};
    #pragma unroll
    for (int kc = 0; kc < 4; kc++){
        const int kb = kc*8 + tig;
        u32 bf0[8], bf1[8];
        #pragma unroll
        for (int nt = 0; nt < 8; nt++){
            int px = nb + nt*8 + gid;
            bf0[nt] = Xnw[px*36 + kb];
            bf1[nt] = Xnw[px*36 + kb + 4];
        }
        #pragma unroll
        for (int mt = 0; mt < 3; mt++){
            int oc = (mg+mt)*16 + gid;
            u32 a0 = Wsw[oc*36 + kb],       a1 = Wsw[(oc+8)*36 + kb];
            u32 a2 = Wsw[oc*36 + kb + 4],   a3 = Wsw[(oc+8)*36 + kb + 4];
            #pragma unroll
            for (int nt = 0; nt < 8; nt++)
                mma16(acc[mt][nt], a0, a1, a2, a3, bf0[nt], bf1[nt]);
        }
    }
    const int pyo = (y&31)*32, wrow = (y>>5)*8;
    #pragma unroll
    for (int mt = 0; mt < 3; mt++){
        int ocA = (mg+mt)*16 + gid, ocB = ocA + 8;
        float bA = g_bqkv[ocA], bB = g_bqkv[ocB];
        int t3A = ocA>>6, cA = ocA&63;
        int t3B = ocB>>6, cB = ocB&63;
        __half* pA = (t3A==0?g_qh:(t3A==1?g_kh:g_vh)) + (u64)(b*8+(cA>>3))*64*EE + (cA&7)*1024;
        __half* pB = (t3B==0?g_qh:(t3B==1?g_kh:g_vh)) + (u64)(b*8+(cB>>3))*64*EE + (cB&7)*1024;
        #pragma unroll
        for (int nt = 0; nt < 8; nt++){
            int px = x0 + nb + nt*8 + tig*2;
            int wo2 = (wrow + (px>>5))*EE + pyo + (px&31);
            *(__half2*)&pA[wo2] = __halves2half2(__float2half_rn(acc[mt][nt][0]+bA),
                                                 __float2half_rn(acc[mt][nt][1]+bA));
            *(__half2*)&pB[wo2] = __halves2half2(__float2half_rn(acc[mt][nt][2]+bB),
                                                 __float2half_rn(acc[mt][nt][3]+bB));
        }
    }
}

// ---------- scores: per (bh, e-slice 512): partial S[64,64] ----------
__global__ __launch_bounds__(128) void attn_scores_kernel(){
    __shared__ __half Qs[64*72];
    __shared__ __half Ks[64*72];
    u32* Qsw = (u32*)Qs; u32* Ksw = (u32*)Ks;
    const int bh = blockIdx.x>>4, sl = blockIdx.x&15, e0 = sl*512;
    const int tid = threadIdx.x, w = tid>>5, gid = (tid&31)>>2, tig = tid&3;
    const u32* Qg = (const u32*)g_qh + (u64)bh*64*4096;
    const u32* Kg = (const u32*)g_kh + (u64)bh*64*4096;
    float acc[8][4] = {};
    for (int ec = 0; ec < 8; ec++){
        __syncthreads();
        const int eoff = (e0 + ec*64)>>1;
        for (int i = tid; i < 2048; i += 128){
            int q = i>>5, ew = i&31;
            Qsw[q*36+ew] = Qg[q*4096 + eoff + ew];
            Ksw[q*36+ew] = Kg[q*4096 + eoff + ew];
        }
        __syncthreads();
        #pragma unroll
        for (int kc = 0; kc < 4; kc++){
            const int kb = kc*8 + tig;
            int qr = w*16 + gid;
            u32 a0 = Qsw[qr*36 + kb],     a1 = Qsw[(qr+8)*36 + kb];
            u32 a2 = Qsw[qr*36 + kb + 4], a3 = Qsw[(qr+8)*36 + kb + 4];
            #pragma unroll
            for (int nt = 0; nt < 8; nt++){
                int key = nt*8 + gid;
                mma16(acc[nt], a0, a1, a2, a3, Ksw[key*36+kb], Ksw[key*36+kb+4]);
            }
        }
    }
    float* Sp = g_Sp + (u64)(sl*64+bh)*4096;
    int qA = w*16+gid, qB = qA+8;
    #pragma unroll
    for (int nt = 0; nt < 8; nt++){
        int key = nt*8 + tig*2;
        *(float2*)&Sp[qA*64+key] = make_float2(acc[nt][0], acc[nt][1]);
        *(float2*)&Sp[qB*64+key] = make_float2(acc[nt][2], acc[nt][3]);
    }
}

// ---------- softmax: one warp per (bh,q) row; P -> fp16 ----------
__global__ void softmax_kernel(){
    const int r = blockIdx.x*8 + (threadIdx.x>>5);
    const int bh = r>>6, q = r&63, lane = threadIdx.x&31;
    const float scale = 0.011048543456039806f;
    float s0 = 0.f, s1 = 0.f;
    #pragma unroll
    for (int sl = 0; sl < 16; sl++){
        const float* p = g_Sp + (u64)(sl*64+bh)*4096 + q*64;
        s0 += p[lane]; s1 += p[lane+32];
    }
    s0 *= scale; s1 *= scale;
    float mx = fmaxf(s0, s1);
    for (int o = 16; o; o >>= 1) mx = fmaxf(mx, __shfl_xor_sync(~0u, mx, o));
    float e0 = __expf(s0-mx), e1 = __expf(s1-mx);
    float sum = e0+e1;
    for (int o = 16; o; o >>= 1) sum += __shfl_xor_sync(~0u, sum, o);
    float inv = 1.f/sum;
    g_P[bh*4096 + q*64 + lane]    = __float2half_rn(e0*inv);
    g_P[bh*4096 + q*64 + lane+32] = __float2half_rn(e1*inv);
}

// ---------- PV: per (bh, e-chunk 256): Y[64q,256e] = P[64,64] V[64,256] ----------
__global__ __launch_bounds__(256) void attn_pv_kernel(){
    extern __shared__ __half smh[];
    __half* Ps = smh;            // [64][72]
    __half* Vs = smh + 4608;     // [256e][72 (keys)]
    u32* Psw = (u32*)Ps; u32* Vsw = (u32*)Vs;
    const int bh = blockIdx.x>>5, ec = blockIdx.x&31, e0 = ec*256;
    const int tid = threadIdx.x, w = tid>>5, gid = (tid&31)>>2, tig = tid&3;
    const u32* Pg = (const u32*)g_P + bh*2048;
    for (int i = tid; i < 2048; i += 256){
        int q = i>>5, kw = i&31;
        Psw[q*36+kw] = Pg[q*32 + kw];
    }
    const u32* Vg = (const u32*)g_vh + (u64)bh*64*4096;
    for (int i = tid; i < 8192; i += 256){
        int key = i>>7, ew = i&127;
        u32 v2 = Vg[key*4096 + (e0>>1) + ew];
        __half2 h = *(__half2*)&v2;
        Vs[(2*ew)*72 + key]   = __low2half(h);
        Vs[(2*ew+1)*72 + key] = __high2half(h);
    }
    __syncthreads();
    const int mw = w&3, eh = w>>2;
    float acc[16][4] = {};
    #pragma unroll
    for (int kc = 0; kc < 4; kc++){
        const int kb = kc*8 + tig;
        int qr = mw*16 + gid;
        u32 a0 = Psw[qr*36 + kb],     a1 = Psw[(qr+8)*36 + kb];
        u32 a2 = Psw[qr*36 + kb + 4], a3 = Psw[(qr+8)*36 + kb + 4];
        #pragma unroll
        for (int nt = 0; nt < 16; nt++){
            int e = eh*128 + nt*8 + gid;
            mma16(acc[nt], a0, a1, a2, a3, Vsw[e*36+kb], Vsw[e*36+kb+4]);
        }
    }
    const int b = bh>>3, h = bh&7;
    const int qA = mw*16+gid, qB = qA+8;
    const int sA = ((qA>>3)*32)*256 + (qA&7)*32;
    const int sB = ((qB>>3)*32)*256 + (qB&7)*32;
    #pragma unroll
    for (int nt = 0; nt < 16; nt++){
        int eg = e0 + eh*128 + nt*8 + tig*2;
        int d = eg>>10, py = (eg>>5)&31, px = eg&31;
        float* base = g_y + (u64)(b*64 + h*8 + d)*HWSZ + py*256 + px;
        *(float2*)&base[sA] = make_float2(acc[nt][0], acc[nt][1]);
        *(float2*)&base[sB] = make_float2(acc[nt][2], acc[nt][3]);
    }
}

// ---------- conv 3x3: tile 8x16 px, M=128, N=64oc, K=9x64 ----------
template<int D>
__global__ __launch_bounds__(128) void conv_mma_kernel(
        const float* __restrict__ src, const __half* __restrict__ gw,
        const float* __restrict__ bias, const float* __restrict__ resid,
        float* __restrict__ dst){
    constexpr int ROWS = 8 + 2*D, COLS = 16 + 2*D, RC = ROWS*COLS;
    extern __shared__ __half smh[];
    __half* In = smh;                // [RC][72 ci]
    __half* Wt = smh + RC*72;        // [64oc][72 ci]
    u32* Inw = (u32*)In; u32* Wtw = (u32*)Wt;
    const int tid = threadIdx.x, w = tid>>5, gid = (tid&31)>>2, tig = tid&3;
    const int b = blockIdx.z, y0 = blockIdx.y*8, x0 = blockIdx.x*16;
    __shared__ int yoff[12], xoff[20];
    if (tid < ROWS) yoff[tid] = refl(y0 - D + tid, HH)*256;
    if (tid >= 32 && tid < 32+COLS) xoff[tid-32] = refl(x0 - D + (tid-32), WW);
    __syncthreads();
    for (int i = tid; i < 64*RC; i += 128){
        int ci = i/RC, rem = i - ci*RC;
        int r = rem/COLS, c = rem - r*COLS;
        In[rem*72 + ci] = __float2half_rn(src[(u64)(b*64+ci)*HWSZ + yoff[r] + xoff[c]]);
    }
    float acc[2][8][4] = {};
    const u32* gww = (const u32*)gw;
    for (int tap = 0; tap < 9; tap++){
        __syncthreads();
        for (int i = tid; i < 2304; i += 128) Wtw[i] = gww[tap*2304 + i];
        __syncthreads();
        const int dy = tap/3, dx = tap - dy*3;
        #pragma unroll
        for (int kc = 0; kc < 4; kc++){
            const int kb = kc*8 + tig;
            u32 bf0[8], bf1[8];
            #pragma unroll
            for (int nt = 0; nt < 8; nt++){
                int oc = nt*8 + gid;
                bf0[nt] = Wtw[oc*36 + kb];
                bf1[nt] = Wtw[oc*36 + kb + 4];
            }
            #pragma unroll
            for (int mt = 0; mt < 2; mt++){
                int pos = (2*w + mt + dy*D)*COLS + gid + dx*D;
                u32 a0 = Inw[pos*36 + kb],       a1 = Inw[(pos+8)*36 + kb];
                u32 a2 = Inw[pos*36 + kb + 4],   a3 = Inw[(pos+8)*36 + kb + 4];
                #pragma unroll
                for (int nt = 0; nt < 8; nt++)
                    mma16(acc[mt][nt], a0, a1, a2, a3, bf0[nt], bf1[nt]);
            }
        }
    }
    float bv0[8], bv1[8];
    #pragma unroll
    for (int nt = 0; nt < 8; nt++){
        bv0[nt] = __ldg(&bias[nt*8 + tig*2]);
        bv1[nt] = __ldg(&bias[nt*8 + tig*2 + 1]);
    }
    #pragma unroll
    for (int mt = 0; mt < 2; mt++){
        const int yy = y0 + w*2 + mt;
        const int rowbase = b*64*HWSZ + yy*256 + x0 + gid;
        #pragma unroll
        for (int nt = 0; nt < 8; nt++){
            const int a00 = rowbase + (nt*8 + tig*2)*HWSZ;
            float v0 = lrelu(acc[mt][nt][0] + bv0[nt]);
            float v1 = lrelu(acc[mt][nt][1] + bv1[nt]);
            float v2 = lrelu(acc[mt][nt][2] + bv0[nt]);
            float v3 = lrelu(acc[mt][nt][3] + bv1[nt]);
            if (resid){
                v0 += resid[a00];
                v1 += resid[a00 + HWSZ];
                v2 += resid[a00 + 8];
                v3 += resid[a00 + HWSZ + 8];
            }
            dst[a00]            = v0;
            dst[a00 + HWSZ]     = v1;
            dst[a00 + 8]        = v2;
            dst[a00 + HWSZ + 8] = v3;
        }
    }
}

extern "C" void kernel_launch(void* const* d_in, const int* in_sizes, int n_in,
                              void* d_out, int out_size){
    const float* x   = (const float*)d_in[0];
    const float* wq  = (const float*)d_in[2];
    const float* bq  = (const float*)d_in[3];
    const float* wk  = (const float*)d_in[4];
    const float* bk  = (const float*)d_in[5];
    const float* wv  = (const float*)d_in[6];
    const float* bv  = (const float*)d_in[7];
    const float* wo  = (const float*)d_in[8];
    const float* bo  = (const float*)d_in[9];
    const float* wf1 = (const float*)d_in[10];
    const float* bf1 = (const float*)d_in[11];
    const float* wf2 = (const float*)d_in[12];
    const float* bf2 = (const float*)d_in[13];
    float* out = (float*)d_out;

    float *py, *px1, *pt; __half* pwt;
    cudaGetSymbolAddress((void**)&py,  g_y);
    cudaGetSymbolAddress((void**)&px1, g_x1);
    cudaGetSymbolAddress((void**)&pt,  g_t);
    cudaGetSymbolAddress((void**)&pwt, g_wth);

    const int QKV_SMEM = (13824 + 128*72) * 2;          // 46080 B
    const int PV_SMEM  = (4608 + 256*72) * 2;           // 46080 B
    const int SM1 = (180*72 + 64*72) * 2;               // 35136 B
    const int SM2 = (240*72 + 64*72) * 2;               // 43776 B
    cudaFuncSetAttribute(qkv_kernel, cudaFuncAttributeMaxDynamicSharedMemorySize, QKV_SMEM);
    cudaFuncSetAttribute(attn_pv_kernel, cudaFuncAttributeMaxDynamicSharedMemorySize, PV_SMEM);
    cudaFuncSetAttribute(conv_mma_kernel<1>, cudaFuncAttributeMaxDynamicSharedMemorySize, SM1);
    cudaFuncSetAttribute(conv_mma_kernel<2>, cudaFuncAttributeMaxDynamicSharedMemorySize, SM2);

    xform_kernel<<<144, 256>>>(wq, bq, wk, bk, wv, bv, wo, wf1, wf2);
    qkv_kernel<<<dim3(2, 256, BB), 256, QKV_SMEM>>>(x);
    attn_scores_kernel<<<1024, 128>>>();
    softmax_kernel<<<512, 256>>>();
    attn_pv_kernel<<<2048, 256, PV_SMEM>>>();
    dim3 cg(16, 32, BB);
    conv_mma_kernel<1><<<cg, 128, SM1>>>(py,  pwt,            bo,  x,       px1);
    conv_mma_kernel<2><<<cg, 128, SM2>>>(px1, pwt + 41472,    bf1, nullptr, pt);
    conv_mma_kernel<1><<<cg, 128, SM1>>>(pt,  pwt + 2*41472,  bf2, px1,     out);
}